// round 14
// baseline (speedup 1.0000x reference)
#include <cuda_runtime.h>
#include <cuda_bf16.h>
#include <math.h>

// Problem constants (fixed shapes from reference)
#define BB 16
#define CC 6
#define QQ 256
#define TT 256
#define DD 256
#define NPAIR 15   // C*(C-1)/2

// Accumulator indices
#define A_SQ    0
#define A_BCE_S 1
#define A_BCE_C 2
#define A_BOX_S 3
#define A_BOX_C 4
#define A_ENT_S 5
#define A_ENT_C 6
#define A_NLL_S 7
#define A_NLL_C 8
#define A_CON_S 9
#define A_CON_C 10
#define A_N     11

__device__ double g_acc[A_N];
__device__ int    g_qids[BB * CC * QQ];
__device__ unsigned char g_qvalid[BB * CC * QQ];
__device__ int    g_cam_stride;
__device__ int    g_tm_stride;

__constant__ int PAIR_C[NPAIR] = {0,0,0,0,0,1,1,1,1,2,2,2,3,3,4};
__constant__ int PAIR_D[NPAIR] = {1,2,3,4,5,2,3,4,5,3,4,5,4,5,5};

// ---------------------------------------------------------------------------
// Fast natural log (cephes logf style), valid for normal positive floats.
// Accuracy ~2 ulp — far inside the 1e-3 rel-err budget, avoids MUFU bottleneck.
__device__ __forceinline__ float fast_logf(float x) {
    int ix = __float_as_int(x);
    int e = ((ix >> 23) & 0xFF) - 126;
    float m = __int_as_float((ix & 0x007FFFFF) | 0x3F000000); // [0.5, 1)
    if (m < 0.70710678118654752440f) { m += m; e -= 1; }      // [0.7071, 1.4142)
    float z = m - 1.0f;
    float p = 7.0376836292e-2f;
    p = fmaf(p, z, -1.1514610310e-1f);
    p = fmaf(p, z,  1.1676998740e-1f);
    p = fmaf(p, z, -1.2420140846e-1f);
    p = fmaf(p, z,  1.4249322787e-1f);
    p = fmaf(p, z, -1.6668057665e-1f);
    p = fmaf(p, z,  2.0000714765e-1f);
    p = fmaf(p, z, -2.4999993993e-1f);
    p = fmaf(p, z,  3.3333331174e-1f);
    float z2 = z * z;
    float y = z2 * fmaf(z, p, -0.5f);
    float ef = (float)e;
    float r = z + fmaf(ef, -2.12194440e-4f, y);
    r = fmaf(ef, 0.693359375f, r);
    return r;
}

__device__ __forceinline__ bool load_mask(const unsigned char* p, int idx, int stride) {
    if (stride == 4) return ((const int*)p)[idx] != 0;
    return p[idx] != 0;
}

__device__ __forceinline__ float block_reduce(float v, float* sbuf) {
    int t = threadIdx.x;
    sbuf[t] = v;
    __syncthreads();
    #pragma unroll
    for (int s = 128; s > 0; s >>= 1) {
        if (t < s) sbuf[t] += sbuf[t + s];
        __syncthreads();
    }
    float r = sbuf[0];
    __syncthreads();
    return r;
}

// ---------------------------------------------------------------------------
// Init: zero accumulators; sniff whether bool masks are uint8 or int32.
__device__ int detect_stride(const unsigned char* p, int nbytes) {
    // int32 bool layout: bytes at offset (i%4)!=0 are all zero.
    bool int32like = true;
    for (int i = 0; i < nbytes; i++) {
        if ((i & 3) != 0 && p[i] != 0) { int32like = false; break; }
    }
    return int32like ? 4 : 1;
}

__global__ void init_kernel(const unsigned char* cam, const unsigned char* tm) {
    if (threadIdx.x == 0) {
        for (int i = 0; i < A_N; i++) g_acc[i] = 0.0;
        g_cam_stride = detect_stride(cam, 96);    // 96 bytes safe either layout
        g_tm_stride  = detect_stride(tm, 256);    // 256 bytes safe either layout
    }
}

__device__ __forceinline__ float read_img_scalar(const int* p, float defv) {
    if (p == nullptr) return defv;
    int v = *p;
    if (v > 0 && v < (1 << 20)) return (float)v;
    float f = __int_as_float(v);
    if (f > 0.0f && f < 1048576.0f) return f;
    return defv;
}

// ---------------------------------------------------------------------------
// Pack kernel: one block per (b,c). Stable partition via prefix scan, writes
// qids/qvalid, and fuses score BCE, box L1, and pair NLL accumulation.
__global__ void pack_kernel(const float* __restrict__ det_scores,
                            const float* __restrict__ det_boxes,
                            const float* __restrict__ assoc,
                            const float* __restrict__ boxes,
                            const unsigned char* __restrict__ cam_mask,
                            const unsigned char* __restrict__ target_mask,
                            const int* __restrict__ ids,
                            const int* p_imgh, const int* p_imgw) {
    __shared__ int pre[QQ];
    __shared__ int order_sh[QQ];
    __shared__ float sred[QQ];

    const int bc = blockIdx.x;           // b*C + c
    const int q  = threadIdx.x;
    const int base = bc * QQ;

    const bool cam = load_mask(cam_mask, bc, g_cam_stride);
    const bool tm  = load_mask(target_mask, base + q, g_tm_stride);

    // inclusive scan of tm
    pre[q] = tm ? 1 : 0;
    __syncthreads();
    for (int off = 1; off < QQ; off <<= 1) {
        int t = (q >= off) ? pre[q - off] : 0;
        __syncthreads();
        pre[q] += t;
        __syncthreads();
    }
    const int count = pre[QQ - 1];
    const int excl_true = pre[q] - (tm ? 1 : 0);
    const int dest = tm ? excl_true : (count + (q - excl_true));
    order_sh[dest] = q;
    __syncthreads();

    const int src = order_sh[q];
    const bool valid = (q < count) && cam;
    const int sid = ids[base + src];
    const int qid = valid ? sid : -1;
    g_qids[base + q] = qid;
    g_qvalid[base + q] = valid ? 1 : 0;

    const float imgh = read_img_scalar(p_imgh, 512.0f);
    const float imgw = read_img_scalar(p_imgw, 512.0f);
    const float inv_norm[4] = {1.0f / imgw, 1.0f / imgh, 1.0f / imgw, 1.0f / imgh};

    // --- score BCE (mask = cam broadcast over all q) ---
    float bce = 0.0f;
    if (cam) {
        float p = det_scores[base + q];
        p = fminf(fmaxf(p, 1e-6f), 1.0f - 1e-6f);
        bce = valid ? -fast_logf(p) : -fast_logf(1.0f - p);
    }

    // --- box L1 (mask = qvalid) ---
    float bsum = 0.0f;
    if (valid) {
        #pragma unroll
        for (int k = 0; k < 4; k++) {
            float bt = boxes[(base + src) * 4 + k] * inv_norm[k];
            bt = fminf(fmaxf(bt, 0.0f), 1.0f);
            bsum += fabsf(det_boxes[(base + q) * 4 + k] - bt);
        }
    }

    // --- pair NLL (mask = qvalid) ---
    float nll = 0.0f;
    if (valid) {
        int slot = qid % TT;
        float a = assoc[(size_t)(base + q) * TT + slot];
        nll = -fast_logf(fmaxf(a, 1e-8f));
    }

    float bce_s = block_reduce(bce, sred);
    float box_s = block_reduce(bsum, sred);
    float nll_s = block_reduce(nll, sred);

    if (q == 0) {
        if (bce_s != 0.0f || cam) atomicAdd(&g_acc[A_BCE_S], (double)bce_s);
        atomicAdd(&g_acc[A_BOX_S], (double)box_s);
        atomicAdd(&g_acc[A_NLL_S], (double)nll_s);
        if (cam) {
            atomicAdd(&g_acc[A_BCE_C], (double)QQ);
            atomicAdd(&g_acc[A_BOX_C], 4.0 * (double)count);
            atomicAdd(&g_acc[A_NLL_C], (double)count);
        }
    }
}

// ---------------------------------------------------------------------------
// det_norm: mean of det_tokens^2 over 6.29M floats (float4 grid-stride).
__global__ void sq_kernel(const float4* __restrict__ x, int n4) {
    __shared__ float sred[256];
    float acc = 0.0f;
    for (int i = blockIdx.x * blockDim.x + threadIdx.x; i < n4; i += gridDim.x * blockDim.x) {
        float4 v = x[i];
        acc = fmaf(v.x, v.x, acc);
        acc = fmaf(v.y, v.y, acc);
        acc = fmaf(v.z, v.z, acc);
        acc = fmaf(v.w, v.w, acc);
    }
    float s = block_reduce(acc, sred);
    if (threadIdx.x == 0) atomicAdd(&g_acc[A_SQ], (double)s);
}

// ---------------------------------------------------------------------------
// Entropy: one block per (b,c,q) row of assoc. Skip rows with cam=0.
__global__ void entropy_kernel(const float* __restrict__ assoc,
                               const unsigned char* __restrict__ cam_mask) {
    __shared__ float sred[TT];
    const int row = blockIdx.x;            // b*C*Q + c*Q + q
    const int bc = row / QQ;
    if (!load_mask(cam_mask, bc, g_cam_stride)) return;
    float a = assoc[(size_t)row * TT + threadIdx.x];
    float logp = fast_logf(fmaxf(a, 1e-8f));
    float s = block_reduce(a * logp, sred);
    if (threadIdx.x == 0) {
        atomicAdd(&g_acc[A_ENT_S], (double)(-s));
        atomicAdd(&g_acc[A_ENT_C], 1.0);
    }
}

// ---------------------------------------------------------------------------
// Consistency: one block per (b, pair(c<d), q). Sparse match on qids.
__global__ void consistency_kernel(const float* __restrict__ assoc) {
    __shared__ int plist[QQ];
    __shared__ int s_cnt;
    __shared__ float sred[TT];

    int blk = blockIdx.x;
    const int q  = blk % QQ;  blk /= QQ;
    const int pr = blk % NPAIR;
    const int b  = blk / NPAIR;
    const int c = PAIR_C[pr];
    const int d = PAIR_D[pr];
    const int cbase = (b * CC + c) * QQ;
    const int dbase = (b * CC + d) * QQ;

    if (!g_qvalid[cbase + q]) return;
    const int myqid = g_qids[cbase + q];

    if (threadIdx.x == 0) s_cnt = 0;
    __syncthreads();

    {
        int p = threadIdx.x;
        if (g_qvalid[dbase + p] && g_qids[dbase + p] == myqid) {
            int i = atomicAdd(&s_cnt, 1);
            plist[i] = p;
        }
    }
    __syncthreads();
    const int cnt = s_cnt;
    if (cnt == 0) return;

    const int t = threadIdx.x;
    float s = 0.0f;
    for (int i = 0; i < cnt; i++) {
        s += assoc[(size_t)(dbase + plist[i]) * TT + t];
    }
    float peer = s / (float)cnt;
    float diff = assoc[(size_t)(cbase + q) * TT + t] - peer;
    float term = block_reduce(diff * diff, sred);
    if (t == 0) {
        atomicAdd(&g_acc[A_CON_S], (double)(term / (float)TT));
        atomicAdd(&g_acc[A_CON_C], 1.0);
    }
}

// ---------------------------------------------------------------------------
// Finalize: combine all accumulators into the 6 output scalars.
__global__ void finalize_kernel(float* __restrict__ out, int out_size) {
    if (threadIdx.x != 0 || blockIdx.x != 0) return;
    double dn    = g_acc[A_SQ] / ((double)BB * CC * QQ * DD);
    double score = g_acc[A_BCE_S] / fmax(g_acc[A_BCE_C], 1.0);
    double boxl  = g_acc[A_BOX_S] / fmax(g_acc[A_BOX_C], 1.0);
    double sup   = score + boxl;
    double ent   = g_acc[A_ENT_S] / fmax(g_acc[A_ENT_C], 1.0);
    double pair  = g_acc[A_NLL_S] / fmax(g_acc[A_NLL_C], 1.0);
    double con   = g_acc[A_CON_S] / fmax(g_acc[A_CON_C], 1.0);
    double tot   = dn + sup + ent + pair + con;
    float vals[6] = {(float)tot, (float)dn, (float)sup, (float)ent, (float)pair, (float)con};
    int n = out_size < 6 ? out_size : 6;
    for (int i = 0; i < n; i++) out[i] = vals[i];
}

// ---------------------------------------------------------------------------
extern "C" void kernel_launch(void* const* d_in, const int* in_sizes, int n_in,
                              void* d_out, int out_size) {
    // Input order (per setup_inputs / reference signature):
    // 0 det_tokens (B,C,Q,D) f32
    // 1 det_scores (B,C,Q)   f32
    // 2 det_boxes  (B,C,Q,4) f32
    // 3 assoc      (B,C,Q,T) f32
    // 4 boxes      (B,C,Q,4) f32
    // 5 cam_mask   (B,C)     bool
    // 6 target_mask(B,C,Q)   bool
    // 7 ids        (B,C,Q)   i32
    // 8 img_h scalar (maybe), 9 img_w scalar (maybe)
    const float* det_tokens = (const float*)d_in[0];
    const float* det_scores = (const float*)d_in[1];
    const float* det_boxes  = (const float*)d_in[2];
    const float* assoc      = (const float*)d_in[3];
    const float* boxes      = (const float*)d_in[4];
    const unsigned char* cam_mask    = (const unsigned char*)d_in[5];
    const unsigned char* target_mask = (const unsigned char*)d_in[6];
    const int* ids = (const int*)d_in[7];
    const int* p_imgh = (n_in >= 10) ? (const int*)d_in[8] : nullptr;
    const int* p_imgw = (n_in >= 10) ? (const int*)d_in[9] : nullptr;
    float* out = (float*)d_out;

    init_kernel<<<1, 32>>>(cam_mask, target_mask);

    pack_kernel<<<BB * CC, QQ>>>(det_scores, det_boxes, assoc, boxes,
                                 cam_mask, target_mask, ids, p_imgh, p_imgw);

    const int n4 = BB * CC * QQ * DD / 4;
    sq_kernel<<<1024, 256>>>((const float4*)det_tokens, n4);

    entropy_kernel<<<BB * CC * QQ, TT>>>(assoc, cam_mask);

    consistency_kernel<<<BB * NPAIR * QQ, TT>>>(assoc);

    finalize_kernel<<<1, 32>>>(out, out_size);
}

// round 15
// speedup vs baseline: 1.3315x; 1.3315x over previous
#include <cuda_runtime.h>
#include <cuda_bf16.h>
#include <math.h>

// Problem constants (fixed shapes from reference)
#define BB 16
#define CC 6
#define QQ 256
#define TT 256
#define DD 256
#define NPAIR 15   // C*(C-1)/2
#define N4 ((BB*CC*QQ*TT)/4)   // float4 count for assoc / det_tokens (both 6.29M floats)

// Accumulator indices
#define A_SQ    0
#define A_BCE_S 1
#define A_BCE_C 2
#define A_BOX_S 3
#define A_BOX_C 4
#define A_ENT_S 5
#define A_ENT_C 6
#define A_NLL_S 7
#define A_NLL_C 8
#define A_CON_S 9
#define A_CON_C 10
#define A_N     11

__device__ double g_acc[A_N];
__device__ int    g_qids[BB * CC * QQ];     // -1 == invalid
__device__ unsigned g_cam_bits[3];          // 96 cams, bit per (b,c)
__device__ int    g_cam_stride;
__device__ int    g_tm_stride;

__constant__ int PAIR_C[NPAIR] = {0,0,0,0,0,1,1,1,1,2,2,2,3,3,4};
__constant__ int PAIR_D[NPAIR] = {1,2,3,4,5,2,3,4,5,3,4,5,4,5,5};

// ---------------------------------------------------------------------------
// Fast natural log (cephes logf style), ~2 ulp. Avoids MUFU bottleneck.
__device__ __forceinline__ float fast_logf(float x) {
    int ix = __float_as_int(x);
    int e = ((ix >> 23) & 0xFF) - 126;
    float m = __int_as_float((ix & 0x007FFFFF) | 0x3F000000); // [0.5, 1)
    if (m < 0.70710678118654752440f) { m += m; e -= 1; }      // [0.7071, 1.4142)
    float z = m - 1.0f;
    float p = 7.0376836292e-2f;
    p = fmaf(p, z, -1.1514610310e-1f);
    p = fmaf(p, z,  1.1676998740e-1f);
    p = fmaf(p, z, -1.2420140846e-1f);
    p = fmaf(p, z,  1.4249322787e-1f);
    p = fmaf(p, z, -1.6668057665e-1f);
    p = fmaf(p, z,  2.0000714765e-1f);
    p = fmaf(p, z, -2.4999993993e-1f);
    p = fmaf(p, z,  3.3333331174e-1f);
    float z2 = z * z;
    float y = z2 * fmaf(z, p, -0.5f);
    float ef = (float)e;
    float r = z + fmaf(ef, -2.12194440e-4f, y);
    r = fmaf(ef, 0.693359375f, r);
    return r;
}

__device__ __forceinline__ bool load_mask(const unsigned char* p, int idx, int stride) {
    if (stride == 4) return ((const int*)p)[idx] != 0;
    return p[idx] != 0;
}

// Warp/block reductions (shuffle-based; result valid in thread 0)
__device__ __forceinline__ float warp_reduce(float v) {
    #pragma unroll
    for (int o = 16; o > 0; o >>= 1) v += __shfl_down_sync(0xFFFFFFFFu, v, o);
    return v;
}
__device__ __forceinline__ float block_reduce256(float v, float* s8) {
    int lane = threadIdx.x & 31, wid = threadIdx.x >> 5;
    v = warp_reduce(v);
    if (lane == 0) s8[wid] = v;
    __syncthreads();
    if (wid == 0) {
        v = (lane < 8) ? s8[lane] : 0.0f;
        v = warp_reduce(v);
    }
    return v;
}

// Legacy full smem reduce for pack kernel (needs 3 reductions, small grid)
__device__ __forceinline__ float block_reduce_smem(float v, float* sbuf) {
    int t = threadIdx.x;
    sbuf[t] = v;
    __syncthreads();
    #pragma unroll
    for (int s = 128; s > 0; s >>= 1) {
        if (t < s) sbuf[t] += sbuf[t + s];
        __syncthreads();
    }
    float r = sbuf[0];
    __syncthreads();
    return r;
}

// ---------------------------------------------------------------------------
// Init: zero accumulators; sniff mask layout; bake cam bitmask.
__device__ int detect_stride(const unsigned char* p, int nbytes) {
    bool int32like = true;
    for (int i = 0; i < nbytes; i++) {
        if ((i & 3) != 0 && p[i] != 0) { int32like = false; break; }
    }
    return int32like ? 4 : 1;
}

__global__ void init_kernel(const unsigned char* cam, const unsigned char* tm) {
    if (threadIdx.x == 0) {
        for (int i = 0; i < A_N; i++) g_acc[i] = 0.0;
        int cs = detect_stride(cam, 96);
        g_cam_stride = cs;
        g_tm_stride  = detect_stride(tm, 256);
        unsigned bits[3] = {0, 0, 0};
        for (int bc = 0; bc < BB * CC; bc++) {
            bool v = (cs == 4) ? (((const int*)cam)[bc] != 0) : (cam[bc] != 0);
            if (v) bits[bc >> 5] |= (1u << (bc & 31));
        }
        g_cam_bits[0] = bits[0]; g_cam_bits[1] = bits[1]; g_cam_bits[2] = bits[2];
    }
}

__device__ __forceinline__ float read_img_scalar(const int* p, float defv) {
    if (p == nullptr) return defv;
    int v = *p;
    if (v > 0 && v < (1 << 20)) return (float)v;
    float f = __int_as_float(v);
    if (f > 0.0f && f < 1048576.0f) return f;
    return defv;
}

// ---------------------------------------------------------------------------
// Pack kernel: one block per (b,c). Stable partition via prefix scan, writes
// qids, and fuses score BCE, box L1, pair NLL, and entropy count.
__global__ void pack_kernel(const float* __restrict__ det_scores,
                            const float* __restrict__ det_boxes,
                            const float* __restrict__ assoc,
                            const float* __restrict__ boxes,
                            const unsigned char* __restrict__ cam_mask,
                            const unsigned char* __restrict__ target_mask,
                            const int* __restrict__ ids,
                            const int* p_imgh, const int* p_imgw) {
    __shared__ int pre[QQ];
    __shared__ int order_sh[QQ];
    __shared__ float sred[QQ];

    const int bc = blockIdx.x;           // b*C + c
    const int q  = threadIdx.x;
    const int base = bc * QQ;

    const bool cam = load_mask(cam_mask, bc, g_cam_stride);
    const bool tm  = load_mask(target_mask, base + q, g_tm_stride);

    // inclusive scan of tm
    pre[q] = tm ? 1 : 0;
    __syncthreads();
    for (int off = 1; off < QQ; off <<= 1) {
        int t = (q >= off) ? pre[q - off] : 0;
        __syncthreads();
        pre[q] += t;
        __syncthreads();
    }
    const int count = pre[QQ - 1];
    const int excl_true = pre[q] - (tm ? 1 : 0);
    const int dest = tm ? excl_true : (count + (q - excl_true));
    order_sh[dest] = q;
    __syncthreads();

    const int src = order_sh[q];
    const bool valid = (q < count) && cam;
    const int sid = ids[base + src];
    const int qid = valid ? sid : -1;
    g_qids[base + q] = qid;

    const float imgh = read_img_scalar(p_imgh, 512.0f);
    const float imgw = read_img_scalar(p_imgw, 512.0f);
    const float inv_norm[4] = {1.0f / imgw, 1.0f / imgh, 1.0f / imgw, 1.0f / imgh};

    // --- score BCE (mask = cam broadcast over all q) ---
    float bce = 0.0f;
    if (cam) {
        float p = det_scores[base + q];
        p = fminf(fmaxf(p, 1e-6f), 1.0f - 1e-6f);
        bce = valid ? -fast_logf(p) : -fast_logf(1.0f - p);
    }

    // --- box L1 (mask = qvalid) ---
    float bsum = 0.0f;
    if (valid) {
        #pragma unroll
        for (int k = 0; k < 4; k++) {
            float bt = boxes[(base + src) * 4 + k] * inv_norm[k];
            bt = fminf(fmaxf(bt, 0.0f), 1.0f);
            bsum += fabsf(det_boxes[(base + q) * 4 + k] - bt);
        }
    }

    // --- pair NLL (mask = qvalid) ---
    float nll = 0.0f;
    if (valid) {
        int slot = qid % TT;
        float a = assoc[(size_t)(base + q) * TT + slot];
        nll = -fast_logf(fmaxf(a, 1e-8f));
    }

    float bce_s = block_reduce_smem(bce, sred);
    float box_s = block_reduce_smem(bsum, sred);
    float nll_s = block_reduce_smem(nll, sred);

    if (q == 0) {
        atomicAdd(&g_acc[A_BCE_S], (double)bce_s);
        atomicAdd(&g_acc[A_BOX_S], (double)box_s);
        atomicAdd(&g_acc[A_NLL_S], (double)nll_s);
        if (cam) {
            atomicAdd(&g_acc[A_BCE_C], (double)QQ);
            atomicAdd(&g_acc[A_BOX_C], 4.0 * (double)count);
            atomicAdd(&g_acc[A_NLL_C], (double)count);
            atomicAdd(&g_acc[A_ENT_C], (double)QQ);
        }
    }
}

// ---------------------------------------------------------------------------
// Fused streaming kernel: blocks [0, ENT_BLOCKS) compute assoc entropy
// (grid-stride float4, cam-masked); blocks [ENT_BLOCKS, TOTAL) compute
// sum(det_tokens^2). One atomicAdd per block.
#define ENT_BLOCKS 592
#define SQ_BLOCKS  592
#define STREAM_BLOCKS (ENT_BLOCKS + SQ_BLOCKS)

__global__ void stream_kernel(const float4* __restrict__ assoc4,
                              const float4* __restrict__ dt4) {
    __shared__ float s8[8];
    int bid = blockIdx.x;
    float acc = 0.0f;
    if (bid < ENT_BLOCKS) {
        const unsigned cb0 = g_cam_bits[0], cb1 = g_cam_bits[1], cb2 = g_cam_bits[2];
        for (int i = bid * 256 + threadIdx.x; i < N4; i += ENT_BLOCKS * 256) {
            int bc = i >> 14;                    // QQ*TT/4 = 16384
            unsigned w = (bc < 32) ? cb0 : (bc < 64 ? cb1 : cb2);
            if (!((w >> (bc & 31)) & 1u)) continue;
            float4 v = __ldg(&assoc4[i]);
            acc = fmaf(v.x, fast_logf(fmaxf(v.x, 1e-8f)), acc);
            acc = fmaf(v.y, fast_logf(fmaxf(v.y, 1e-8f)), acc);
            acc = fmaf(v.z, fast_logf(fmaxf(v.z, 1e-8f)), acc);
            acc = fmaf(v.w, fast_logf(fmaxf(v.w, 1e-8f)), acc);
        }
        float s = block_reduce256(acc, s8);
        if (threadIdx.x == 0) atomicAdd(&g_acc[A_ENT_S], (double)(-s));
    } else {
        bid -= ENT_BLOCKS;
        for (int i = bid * 256 + threadIdx.x; i < N4; i += SQ_BLOCKS * 256) {
            float4 v = __ldg(&dt4[i]);
            acc = fmaf(v.x, v.x, acc);
            acc = fmaf(v.y, v.y, acc);
            acc = fmaf(v.z, v.z, acc);
            acc = fmaf(v.w, v.w, acc);
        }
        float s = block_reduce256(acc, s8);
        if (threadIdx.x == 0) atomicAdd(&g_acc[A_SQ], (double)s);
    }
}

// ---------------------------------------------------------------------------
// Consistency: one block per (b, pair(c<d)) = 240 blocks.
// Phase A: per-q match bitmask over the other camera's 256 slots (smem).
// Phase B: deterministic sweep over matched q's with full-block row math.
__global__ void consistency_kernel(const float* __restrict__ assoc) {
    __shared__ int qid_d[QQ];
    __shared__ unsigned mbits[QQ][8];   // 8 KB
    __shared__ int cntarr[QQ];
    __shared__ float s8[8];

    int blk = blockIdx.x;
    const int pr = blk % NPAIR;
    const int b  = blk / NPAIR;
    const int c = PAIR_C[pr];
    const int d = PAIR_D[pr];
    const int cbase = (b * CC + c) * QQ;
    const int dbase = (b * CC + d) * QQ;
    const int t = threadIdx.x;

    const int myqid = g_qids[cbase + t];   // -1 == invalid (this thread's q row)
    qid_d[t] = g_qids[dbase + t];
    __syncthreads();

    // Phase A: thread t builds match bitmask for q = t
    int cnt = 0;
    #pragma unroll
    for (int w = 0; w < 8; w++) {
        unsigned m = 0;
        if (myqid >= 0) {
            #pragma unroll 8
            for (int j = 0; j < 32; j++) {
                if (qid_d[w * 32 + j] == myqid) m |= (1u << j);
            }
        }
        mbits[t][w] = m;
        cnt += __popc(m);
    }
    cntarr[t] = cnt;
    __syncthreads();

    // Phase B: sweep matched q's (deterministic order)
    float con_local = 0.0f;   // meaningful in thread 0 only
    int   rows_local = 0;
    for (int q = 0; q < QQ; q++) {
        const int cq = cntarr[q];
        if (cq == 0) continue;
        float s = 0.0f;
        #pragma unroll
        for (int w = 0; w < 8; w++) {
            unsigned m = mbits[q][w];
            while (m) {
                int j = __ffs(m) - 1;
                m &= m - 1;
                s += __ldg(&assoc[(size_t)(dbase + w * 32 + j) * TT + t]);
            }
        }
        float peer = s / (float)cq;
        float diff = __ldg(&assoc[(size_t)(cbase + q) * TT + t]) - peer;
        float term = block_reduce256(diff * diff, s8);
        if (t == 0) { con_local += term * (1.0f / (float)TT); rows_local++; }
        __syncthreads();   // protect s8 reuse across iterations
    }
    if (t == 0 && rows_local > 0) {
        atomicAdd(&g_acc[A_CON_S], (double)con_local);
        atomicAdd(&g_acc[A_CON_C], (double)rows_local);
    }
}

// ---------------------------------------------------------------------------
// Finalize: combine all accumulators into the 6 output scalars.
__global__ void finalize_kernel(float* __restrict__ out, int out_size) {
    if (threadIdx.x != 0 || blockIdx.x != 0) return;
    double dn    = g_acc[A_SQ] / ((double)BB * CC * QQ * DD);
    double score = g_acc[A_BCE_S] / fmax(g_acc[A_BCE_C], 1.0);
    double boxl  = g_acc[A_BOX_S] / fmax(g_acc[A_BOX_C], 1.0);
    double sup   = score + boxl;
    double ent   = g_acc[A_ENT_S] / fmax(g_acc[A_ENT_C], 1.0);
    double pair  = g_acc[A_NLL_S] / fmax(g_acc[A_NLL_C], 1.0);
    double con   = g_acc[A_CON_S] / fmax(g_acc[A_CON_C], 1.0);
    double tot   = dn + sup + ent + pair + con;
    float vals[6] = {(float)tot, (float)dn, (float)sup, (float)ent, (float)pair, (float)con};
    int n = out_size < 6 ? out_size : 6;
    for (int i = 0; i < n; i++) out[i] = vals[i];
}

// ---------------------------------------------------------------------------
extern "C" void kernel_launch(void* const* d_in, const int* in_sizes, int n_in,
                              void* d_out, int out_size) {
    const float* det_tokens = (const float*)d_in[0];
    const float* det_scores = (const float*)d_in[1];
    const float* det_boxes  = (const float*)d_in[2];
    const float* assoc      = (const float*)d_in[3];
    const float* boxes      = (const float*)d_in[4];
    const unsigned char* cam_mask    = (const unsigned char*)d_in[5];
    const unsigned char* target_mask = (const unsigned char*)d_in[6];
    const int* ids = (const int*)d_in[7];
    const int* p_imgh = (n_in >= 10) ? (const int*)d_in[8] : nullptr;
    const int* p_imgw = (n_in >= 10) ? (const int*)d_in[9] : nullptr;
    float* out = (float*)d_out;

    init_kernel<<<1, 32>>>(cam_mask, target_mask);

    pack_kernel<<<BB * CC, QQ>>>(det_scores, det_boxes, assoc, boxes,
                                 cam_mask, target_mask, ids, p_imgh, p_imgw);

    stream_kernel<<<STREAM_BLOCKS, 256>>>((const float4*)assoc,
                                          (const float4*)det_tokens);

    consistency_kernel<<<BB * NPAIR, 256>>>(assoc);

    finalize_kernel<<<1, 32>>>(out, out_size);
}

// round 16
// speedup vs baseline: 1.3319x; 1.0003x over previous
#include <cuda_runtime.h>
#include <cuda_bf16.h>
#include <math.h>

// Problem constants (fixed shapes from reference)
#define BB 16
#define CC 6
#define QQ 256
#define TT 256
#define DD 256
#define NPAIR 15   // C*(C-1)/2
#define N4 ((BB*CC*QQ*TT)/4)   // float4 count for assoc / det_tokens (both 6.29M floats)

// Accumulator indices
#define A_SQ    0
#define A_BCE_S 1
#define A_BCE_C 2
#define A_BOX_S 3
#define A_BOX_C 4
#define A_ENT_S 5
#define A_ENT_C 6
#define A_NLL_S 7
#define A_NLL_C 8
#define A_CON_S 9
#define A_CON_C 10
#define A_N     11

__device__ double g_acc[A_N];
__device__ int    g_qids[BB * CC * QQ];     // -1 == invalid
__device__ unsigned g_cam_bits[3];          // 96 cams, bit per (b,c)
__device__ int    g_cam_stride;
__device__ int    g_tm_stride;

__constant__ int PAIR_C[NPAIR] = {0,0,0,0,0,1,1,1,1,2,2,2,3,3,4};
__constant__ int PAIR_D[NPAIR] = {1,2,3,4,5,2,3,4,5,3,4,5,4,5,5};

// ---------------------------------------------------------------------------
// Fast natural log (cephes logf style), ~2 ulp. Avoids MUFU bottleneck.
__device__ __forceinline__ float fast_logf(float x) {
    int ix = __float_as_int(x);
    int e = ((ix >> 23) & 0xFF) - 126;
    float m = __int_as_float((ix & 0x007FFFFF) | 0x3F000000); // [0.5, 1)
    if (m < 0.70710678118654752440f) { m += m; e -= 1; }      // [0.7071, 1.4142)
    float z = m - 1.0f;
    float p = 7.0376836292e-2f;
    p = fmaf(p, z, -1.1514610310e-1f);
    p = fmaf(p, z,  1.1676998740e-1f);
    p = fmaf(p, z, -1.2420140846e-1f);
    p = fmaf(p, z,  1.4249322787e-1f);
    p = fmaf(p, z, -1.6668057665e-1f);
    p = fmaf(p, z,  2.0000714765e-1f);
    p = fmaf(p, z, -2.4999993993e-1f);
    p = fmaf(p, z,  3.3333331174e-1f);
    float z2 = z * z;
    float y = z2 * fmaf(z, p, -0.5f);
    float ef = (float)e;
    float r = z + fmaf(ef, -2.12194440e-4f, y);
    r = fmaf(ef, 0.693359375f, r);
    return r;
}

__device__ __forceinline__ bool load_mask(const unsigned char* p, int idx, int stride) {
    if (stride == 4) return ((const int*)p)[idx] != 0;
    return p[idx] != 0;
}

// Warp/block reductions (shuffle-based; result valid in thread 0)
__device__ __forceinline__ float warp_reduce(float v) {
    #pragma unroll
    for (int o = 16; o > 0; o >>= 1) v += __shfl_down_sync(0xFFFFFFFFu, v, o);
    return v;
}
__device__ __forceinline__ float block_reduce256(float v, float* s8) {
    int lane = threadIdx.x & 31, wid = threadIdx.x >> 5;
    v = warp_reduce(v);
    if (lane == 0) s8[wid] = v;
    __syncthreads();
    if (wid == 0) {
        v = (lane < 8) ? s8[lane] : 0.0f;
        v = warp_reduce(v);
    }
    return v;
}

// Legacy full smem reduce for pack kernel (needs 3 reductions, small grid)
__device__ __forceinline__ float block_reduce_smem(float v, float* sbuf) {
    int t = threadIdx.x;
    sbuf[t] = v;
    __syncthreads();
    #pragma unroll
    for (int s = 128; s > 0; s >>= 1) {
        if (t < s) sbuf[t] += sbuf[t + s];
        __syncthreads();
    }
    float r = sbuf[0];
    __syncthreads();
    return r;
}

// ---------------------------------------------------------------------------
// Init: zero accumulators; sniff mask layout; bake cam bitmask.
__device__ int detect_stride(const unsigned char* p, int nbytes) {
    bool int32like = true;
    for (int i = 0; i < nbytes; i++) {
        if ((i & 3) != 0 && p[i] != 0) { int32like = false; break; }
    }
    return int32like ? 4 : 1;
}

__global__ void init_kernel(const unsigned char* cam, const unsigned char* tm) {
    if (threadIdx.x == 0) {
        for (int i = 0; i < A_N; i++) g_acc[i] = 0.0;
        int cs = detect_stride(cam, 96);
        g_cam_stride = cs;
        g_tm_stride  = detect_stride(tm, 256);
        unsigned bits[3] = {0, 0, 0};
        for (int bc = 0; bc < BB * CC; bc++) {
            bool v = (cs == 4) ? (((const int*)cam)[bc] != 0) : (cam[bc] != 0);
            if (v) bits[bc >> 5] |= (1u << (bc & 31));
        }
        g_cam_bits[0] = bits[0]; g_cam_bits[1] = bits[1]; g_cam_bits[2] = bits[2];
    }
}

__device__ __forceinline__ float read_img_scalar(const int* p, float defv) {
    if (p == nullptr) return defv;
    int v = *p;
    if (v > 0 && v < (1 << 20)) return (float)v;
    float f = __int_as_float(v);
    if (f > 0.0f && f < 1048576.0f) return f;
    return defv;
}

// ---------------------------------------------------------------------------
// Pack kernel: one block per (b,c). Stable partition via prefix scan, writes
// qids, and fuses score BCE, box L1, pair NLL, and entropy count.
__global__ void pack_kernel(const float* __restrict__ det_scores,
                            const float* __restrict__ det_boxes,
                            const float* __restrict__ assoc,
                            const float* __restrict__ boxes,
                            const unsigned char* __restrict__ cam_mask,
                            const unsigned char* __restrict__ target_mask,
                            const int* __restrict__ ids,
                            const int* p_imgh, const int* p_imgw) {
    __shared__ int pre[QQ];
    __shared__ int order_sh[QQ];
    __shared__ float sred[QQ];

    const int bc = blockIdx.x;           // b*C + c
    const int q  = threadIdx.x;
    const int base = bc * QQ;

    const bool cam = load_mask(cam_mask, bc, g_cam_stride);
    const bool tm  = load_mask(target_mask, base + q, g_tm_stride);

    // inclusive scan of tm
    pre[q] = tm ? 1 : 0;
    __syncthreads();
    for (int off = 1; off < QQ; off <<= 1) {
        int t = (q >= off) ? pre[q - off] : 0;
        __syncthreads();
        pre[q] += t;
        __syncthreads();
    }
    const int count = pre[QQ - 1];
    const int excl_true = pre[q] - (tm ? 1 : 0);
    const int dest = tm ? excl_true : (count + (q - excl_true));
    order_sh[dest] = q;
    __syncthreads();

    const int src = order_sh[q];
    const bool valid = (q < count) && cam;
    const int sid = ids[base + src];
    const int qid = valid ? sid : -1;
    g_qids[base + q] = qid;

    const float imgh = read_img_scalar(p_imgh, 512.0f);
    const float imgw = read_img_scalar(p_imgw, 512.0f);
    const float inv_norm[4] = {1.0f / imgw, 1.0f / imgh, 1.0f / imgw, 1.0f / imgh};

    // --- score BCE (mask = cam broadcast over all q) ---
    float bce = 0.0f;
    if (cam) {
        float p = det_scores[base + q];
        p = fminf(fmaxf(p, 1e-6f), 1.0f - 1e-6f);
        bce = valid ? -fast_logf(p) : -fast_logf(1.0f - p);
    }

    // --- box L1 (mask = qvalid) ---
    float bsum = 0.0f;
    if (valid) {
        #pragma unroll
        for (int k = 0; k < 4; k++) {
            float bt = boxes[(base + src) * 4 + k] * inv_norm[k];
            bt = fminf(fmaxf(bt, 0.0f), 1.0f);
            bsum += fabsf(det_boxes[(base + q) * 4 + k] - bt);
        }
    }

    // --- pair NLL (mask = qvalid) ---
    float nll = 0.0f;
    if (valid) {
        int slot = qid % TT;
        float a = assoc[(size_t)(base + q) * TT + slot];
        nll = -fast_logf(fmaxf(a, 1e-8f));
    }

    float bce_s = block_reduce_smem(bce, sred);
    float box_s = block_reduce_smem(bsum, sred);
    float nll_s = block_reduce_smem(nll, sred);

    if (q == 0) {
        atomicAdd(&g_acc[A_BCE_S], (double)bce_s);
        atomicAdd(&g_acc[A_BOX_S], (double)box_s);
        atomicAdd(&g_acc[A_NLL_S], (double)nll_s);
        if (cam) {
            atomicAdd(&g_acc[A_BCE_C], (double)QQ);
            atomicAdd(&g_acc[A_BOX_C], 4.0 * (double)count);
            atomicAdd(&g_acc[A_NLL_C], (double)count);
            atomicAdd(&g_acc[A_ENT_C], (double)QQ);
        }
    }
}

// ---------------------------------------------------------------------------
// Fused streaming kernel: blocks [0, ENT_BLOCKS) compute assoc entropy
// (grid-stride float4, cam-masked); blocks [ENT_BLOCKS, TOTAL) compute
// sum(det_tokens^2). One atomicAdd per block.
#define ENT_BLOCKS 592
#define SQ_BLOCKS  592
#define STREAM_BLOCKS (ENT_BLOCKS + SQ_BLOCKS)

__global__ void stream_kernel(const float4* __restrict__ assoc4,
                              const float4* __restrict__ dt4) {
    __shared__ float s8[8];
    int bid = blockIdx.x;
    float acc = 0.0f;
    if (bid < ENT_BLOCKS) {
        const unsigned cb0 = g_cam_bits[0], cb1 = g_cam_bits[1], cb2 = g_cam_bits[2];
        for (int i = bid * 256 + threadIdx.x; i < N4; i += ENT_BLOCKS * 256) {
            int bc = i >> 14;                    // QQ*TT/4 = 16384
            unsigned w = (bc < 32) ? cb0 : (bc < 64 ? cb1 : cb2);
            if (!((w >> (bc & 31)) & 1u)) continue;
            float4 v = __ldg(&assoc4[i]);
            acc = fmaf(v.x, fast_logf(fmaxf(v.x, 1e-8f)), acc);
            acc = fmaf(v.y, fast_logf(fmaxf(v.y, 1e-8f)), acc);
            acc = fmaf(v.z, fast_logf(fmaxf(v.z, 1e-8f)), acc);
            acc = fmaf(v.w, fast_logf(fmaxf(v.w, 1e-8f)), acc);
        }
        float s = block_reduce256(acc, s8);
        if (threadIdx.x == 0) atomicAdd(&g_acc[A_ENT_S], (double)(-s));
    } else {
        bid -= ENT_BLOCKS;
        for (int i = bid * 256 + threadIdx.x; i < N4; i += SQ_BLOCKS * 256) {
            float4 v = __ldg(&dt4[i]);
            acc = fmaf(v.x, v.x, acc);
            acc = fmaf(v.y, v.y, acc);
            acc = fmaf(v.z, v.z, acc);
            acc = fmaf(v.w, v.w, acc);
        }
        float s = block_reduce256(acc, s8);
        if (threadIdx.x == 0) atomicAdd(&g_acc[A_SQ], (double)s);
    }
}

// ---------------------------------------------------------------------------
// Consistency: one block per (b, pair(c<d)) = 240 blocks.
// Phase A: per-q match bitmask over the other camera's 256 slots (smem).
// Phase B: deterministic sweep over matched q's with full-block row math.
__global__ void consistency_kernel(const float* __restrict__ assoc) {
    __shared__ int qid_d[QQ];
    __shared__ unsigned mbits[QQ][8];   // 8 KB
    __shared__ int cntarr[QQ];
    __shared__ float s8[8];

    int blk = blockIdx.x;
    const int pr = blk % NPAIR;
    const int b  = blk / NPAIR;
    const int c = PAIR_C[pr];
    const int d = PAIR_D[pr];
    const int cbase = (b * CC + c) * QQ;
    const int dbase = (b * CC + d) * QQ;
    const int t = threadIdx.x;

    const int myqid = g_qids[cbase + t];   // -1 == invalid (this thread's q row)
    qid_d[t] = g_qids[dbase + t];
    __syncthreads();

    // Phase A: thread t builds match bitmask for q = t
    int cnt = 0;
    #pragma unroll
    for (int w = 0; w < 8; w++) {
        unsigned m = 0;
        if (myqid >= 0) {
            #pragma unroll 8
            for (int j = 0; j < 32; j++) {
                if (qid_d[w * 32 + j] == myqid) m |= (1u << j);
            }
        }
        mbits[t][w] = m;
        cnt += __popc(m);
    }
    cntarr[t] = cnt;
    __syncthreads();

    // Phase B: sweep matched q's (deterministic order)
    float con_local = 0.0f;   // meaningful in thread 0 only
    int   rows_local = 0;
    for (int q = 0; q < QQ; q++) {
        const int cq = cntarr[q];
        if (cq == 0) continue;
        float s = 0.0f;
        #pragma unroll
        for (int w = 0; w < 8; w++) {
            unsigned m = mbits[q][w];
            while (m) {
                int j = __ffs(m) - 1;
                m &= m - 1;
                s += __ldg(&assoc[(size_t)(dbase + w * 32 + j) * TT + t]);
            }
        }
        float peer = s / (float)cq;
        float diff = __ldg(&assoc[(size_t)(cbase + q) * TT + t]) - peer;
        float term = block_reduce256(diff * diff, s8);
        if (t == 0) { con_local += term * (1.0f / (float)TT); rows_local++; }
        __syncthreads();   // protect s8 reuse across iterations
    }
    if (t == 0 && rows_local > 0) {
        atomicAdd(&g_acc[A_CON_S], (double)con_local);
        atomicAdd(&g_acc[A_CON_C], (double)rows_local);
    }
}

// ---------------------------------------------------------------------------
// Finalize: combine all accumulators into the 6 output scalars.
__global__ void finalize_kernel(float* __restrict__ out, int out_size) {
    if (threadIdx.x != 0 || blockIdx.x != 0) return;
    double dn    = g_acc[A_SQ] / ((double)BB * CC * QQ * DD);
    double score = g_acc[A_BCE_S] / fmax(g_acc[A_BCE_C], 1.0);
    double boxl  = g_acc[A_BOX_S] / fmax(g_acc[A_BOX_C], 1.0);
    double sup   = score + boxl;
    double ent   = g_acc[A_ENT_S] / fmax(g_acc[A_ENT_C], 1.0);
    double pair  = g_acc[A_NLL_S] / fmax(g_acc[A_NLL_C], 1.0);
    double con   = g_acc[A_CON_S] / fmax(g_acc[A_CON_C], 1.0);
    double tot   = dn + sup + ent + pair + con;
    float vals[6] = {(float)tot, (float)dn, (float)sup, (float)ent, (float)pair, (float)con};
    int n = out_size < 6 ? out_size : 6;
    for (int i = 0; i < n; i++) out[i] = vals[i];
}

// ---------------------------------------------------------------------------
extern "C" void kernel_launch(void* const* d_in, const int* in_sizes, int n_in,
                              void* d_out, int out_size) {
    const float* det_tokens = (const float*)d_in[0];
    const float* det_scores = (const float*)d_in[1];
    const float* det_boxes  = (const float*)d_in[2];
    const float* assoc      = (const float*)d_in[3];
    const float* boxes      = (const float*)d_in[4];
    const unsigned char* cam_mask    = (const unsigned char*)d_in[5];
    const unsigned char* target_mask = (const unsigned char*)d_in[6];
    const int* ids = (const int*)d_in[7];
    const int* p_imgh = (n_in >= 10) ? (const int*)d_in[8] : nullptr;
    const int* p_imgw = (n_in >= 10) ? (const int*)d_in[9] : nullptr;
    float* out = (float*)d_out;

    init_kernel<<<1, 32>>>(cam_mask, target_mask);

    pack_kernel<<<BB * CC, QQ>>>(det_scores, det_boxes, assoc, boxes,
                                 cam_mask, target_mask, ids, p_imgh, p_imgw);

    stream_kernel<<<STREAM_BLOCKS, 256>>>((const float4*)assoc,
                                          (const float4*)det_tokens);

    consistency_kernel<<<BB * NPAIR, 256>>>(assoc);

    finalize_kernel<<<1, 32>>>(out, out_size);
}

// round 17
// speedup vs baseline: 1.3367x; 1.0036x over previous
#include <cuda_runtime.h>
#include <cuda_bf16.h>
#include <math.h>

// Problem constants (fixed shapes from reference)
#define BB 16
#define CC 6
#define QQ 256
#define TT 256
#define DD 256
#define NPAIR 15   // C*(C-1)/2
#define N4 ((BB*CC*QQ*TT)/4)   // float4 count for assoc / det_tokens (both 6.29M floats)

// Accumulator indices
#define A_SQ    0
#define A_BCE_S 1
#define A_BCE_C 2
#define A_BOX_S 3
#define A_BOX_C 4
#define A_ENT_S 5
#define A_ENT_C 6
#define A_NLL_S 7
#define A_NLL_C 8
#define A_CON_S 9
#define A_CON_C 10
#define A_N     11

__device__ double g_acc[A_N];
__device__ int    g_qids[BB * CC * QQ];     // -1 == invalid
__device__ unsigned g_cam_bits[3];          // 96 cams, bit per (b,c)
__device__ int    g_cam_stride;
__device__ int    g_tm_stride;

__constant__ int PAIR_C[NPAIR] = {0,0,0,0,0,1,1,1,1,2,2,2,3,3,4};
__constant__ int PAIR_D[NPAIR] = {1,2,3,4,5,2,3,4,5,3,4,5,4,5,5};

// ---------------------------------------------------------------------------
// Fast natural log (cephes logf style), ~2 ulp. Avoids MUFU bottleneck.
__device__ __forceinline__ float fast_logf(float x) {
    int ix = __float_as_int(x);
    int e = ((ix >> 23) & 0xFF) - 126;
    float m = __int_as_float((ix & 0x007FFFFF) | 0x3F000000); // [0.5, 1)
    if (m < 0.70710678118654752440f) { m += m; e -= 1; }      // [0.7071, 1.4142)
    float z = m - 1.0f;
    float p = 7.0376836292e-2f;
    p = fmaf(p, z, -1.1514610310e-1f);
    p = fmaf(p, z,  1.1676998740e-1f);
    p = fmaf(p, z, -1.2420140846e-1f);
    p = fmaf(p, z,  1.4249322787e-1f);
    p = fmaf(p, z, -1.6668057665e-1f);
    p = fmaf(p, z,  2.0000714765e-1f);
    p = fmaf(p, z, -2.4999993993e-1f);
    p = fmaf(p, z,  3.3333331174e-1f);
    float z2 = z * z;
    float y = z2 * fmaf(z, p, -0.5f);
    float ef = (float)e;
    float r = z + fmaf(ef, -2.12194440e-4f, y);
    r = fmaf(ef, 0.693359375f, r);
    return r;
}

__device__ __forceinline__ bool load_mask(const unsigned char* p, int idx, int stride) {
    if (stride == 4) return ((const int*)p)[idx] != 0;
    return p[idx] != 0;
}

// Warp/block reductions (shuffle-based; result valid in thread 0)
__device__ __forceinline__ float warp_reduce(float v) {
    #pragma unroll
    for (int o = 16; o > 0; o >>= 1) v += __shfl_down_sync(0xFFFFFFFFu, v, o);
    return v;
}
__device__ __forceinline__ float block_reduce256(float v, float* s8) {
    int lane = threadIdx.x & 31, wid = threadIdx.x >> 5;
    v = warp_reduce(v);
    if (lane == 0) s8[wid] = v;
    __syncthreads();
    if (wid == 0) {
        v = (lane < 8) ? s8[lane] : 0.0f;
        v = warp_reduce(v);
    }
    return v;
}

// Legacy full smem reduce for pack kernel (needs 3 reductions, small grid)
__device__ __forceinline__ float block_reduce_smem(float v, float* sbuf) {
    int t = threadIdx.x;
    sbuf[t] = v;
    __syncthreads();
    #pragma unroll
    for (int s = 128; s > 0; s >>= 1) {
        if (t < s) sbuf[t] += sbuf[t + s];
        __syncthreads();
    }
    float r = sbuf[0];
    __syncthreads();
    return r;
}

// ---------------------------------------------------------------------------
// Init: zero accumulators; sniff mask layout; bake cam bitmask.
__device__ int detect_stride(const unsigned char* p, int nbytes) {
    bool int32like = true;
    for (int i = 0; i < nbytes; i++) {
        if ((i & 3) != 0 && p[i] != 0) { int32like = false; break; }
    }
    return int32like ? 4 : 1;
}

__global__ void init_kernel(const unsigned char* cam, const unsigned char* tm) {
    if (threadIdx.x == 0) {
        for (int i = 0; i < A_N; i++) g_acc[i] = 0.0;
        int cs = detect_stride(cam, 96);
        g_cam_stride = cs;
        g_tm_stride  = detect_stride(tm, 256);
        unsigned bits[3] = {0, 0, 0};
        for (int bc = 0; bc < BB * CC; bc++) {
            bool v = (cs == 4) ? (((const int*)cam)[bc] != 0) : (cam[bc] != 0);
            if (v) bits[bc >> 5] |= (1u << (bc & 31));
        }
        g_cam_bits[0] = bits[0]; g_cam_bits[1] = bits[1]; g_cam_bits[2] = bits[2];
    }
}

__device__ __forceinline__ float read_img_scalar(const int* p, float defv) {
    if (p == nullptr) return defv;
    int v = *p;
    if (v > 0 && v < (1 << 20)) return (float)v;
    float f = __int_as_float(v);
    if (f > 0.0f && f < 1048576.0f) return f;
    return defv;
}

// ---------------------------------------------------------------------------
// Pack kernel: one block per (b,c). Stable partition via prefix scan, writes
// qids, and fuses score BCE, box L1, pair NLL, and entropy count.
__global__ void pack_kernel(const float* __restrict__ det_scores,
                            const float* __restrict__ det_boxes,
                            const float* __restrict__ assoc,
                            const float* __restrict__ boxes,
                            const unsigned char* __restrict__ cam_mask,
                            const unsigned char* __restrict__ target_mask,
                            const int* __restrict__ ids,
                            const int* p_imgh, const int* p_imgw) {
    __shared__ int pre[QQ];
    __shared__ int order_sh[QQ];
    __shared__ float sred[QQ];

    const int bc = blockIdx.x;           // b*C + c
    const int q  = threadIdx.x;
    const int base = bc * QQ;

    const bool cam = load_mask(cam_mask, bc, g_cam_stride);
    const bool tm  = load_mask(target_mask, base + q, g_tm_stride);

    // inclusive scan of tm
    pre[q] = tm ? 1 : 0;
    __syncthreads();
    for (int off = 1; off < QQ; off <<= 1) {
        int t = (q >= off) ? pre[q - off] : 0;
        __syncthreads();
        pre[q] += t;
        __syncthreads();
    }
    const int count = pre[QQ - 1];
    const int excl_true = pre[q] - (tm ? 1 : 0);
    const int dest = tm ? excl_true : (count + (q - excl_true));
    order_sh[dest] = q;
    __syncthreads();

    const int src = order_sh[q];
    const bool valid = (q < count) && cam;
    const int sid = ids[base + src];
    const int qid = valid ? sid : -1;
    g_qids[base + q] = qid;

    const float imgh = read_img_scalar(p_imgh, 512.0f);
    const float imgw = read_img_scalar(p_imgw, 512.0f);
    const float inv_norm[4] = {1.0f / imgw, 1.0f / imgh, 1.0f / imgw, 1.0f / imgh};

    // --- score BCE (mask = cam broadcast over all q) ---
    float bce = 0.0f;
    if (cam) {
        float p = det_scores[base + q];
        p = fminf(fmaxf(p, 1e-6f), 1.0f - 1e-6f);
        bce = valid ? -fast_logf(p) : -fast_logf(1.0f - p);
    }

    // --- box L1 (mask = qvalid) ---
    float bsum = 0.0f;
    if (valid) {
        #pragma unroll
        for (int k = 0; k < 4; k++) {
            float bt = boxes[(base + src) * 4 + k] * inv_norm[k];
            bt = fminf(fmaxf(bt, 0.0f), 1.0f);
            bsum += fabsf(det_boxes[(base + q) * 4 + k] - bt);
        }
    }

    // --- pair NLL (mask = qvalid) ---
    float nll = 0.0f;
    if (valid) {
        int slot = qid % TT;
        float a = assoc[(size_t)(base + q) * TT + slot];
        nll = -fast_logf(fmaxf(a, 1e-8f));
    }

    float bce_s = block_reduce_smem(bce, sred);
    float box_s = block_reduce_smem(bsum, sred);
    float nll_s = block_reduce_smem(nll, sred);

    if (q == 0) {
        atomicAdd(&g_acc[A_BCE_S], (double)bce_s);
        atomicAdd(&g_acc[A_BOX_S], (double)box_s);
        atomicAdd(&g_acc[A_NLL_S], (double)nll_s);
        if (cam) {
            atomicAdd(&g_acc[A_BCE_C], (double)QQ);
            atomicAdd(&g_acc[A_BOX_C], 4.0 * (double)count);
            atomicAdd(&g_acc[A_NLL_C], (double)count);
            atomicAdd(&g_acc[A_ENT_C], (double)QQ);
        }
    }
}

// ---------------------------------------------------------------------------
// Fused streaming kernel: blocks [0, ENT_BLOCKS) compute assoc entropy
// (grid-stride float4, cam-masked); blocks [ENT_BLOCKS, TOTAL) compute
// sum(det_tokens^2). One atomicAdd per block.
#define ENT_BLOCKS 592
#define SQ_BLOCKS  592
#define STREAM_BLOCKS (ENT_BLOCKS + SQ_BLOCKS)

__global__ void stream_kernel(const float4* __restrict__ assoc4,
                              const float4* __restrict__ dt4) {
    __shared__ float s8[8];
    int bid = blockIdx.x;
    float acc = 0.0f;
    if (bid < ENT_BLOCKS) {
        const unsigned cb0 = g_cam_bits[0], cb1 = g_cam_bits[1], cb2 = g_cam_bits[2];
        for (int i = bid * 256 + threadIdx.x; i < N4; i += ENT_BLOCKS * 256) {
            int bc = i >> 14;                    // QQ*TT/4 = 16384
            unsigned w = (bc < 32) ? cb0 : (bc < 64 ? cb1 : cb2);
            if (!((w >> (bc & 31)) & 1u)) continue;
            float4 v = __ldg(&assoc4[i]);
            acc = fmaf(v.x, fast_logf(fmaxf(v.x, 1e-8f)), acc);
            acc = fmaf(v.y, fast_logf(fmaxf(v.y, 1e-8f)), acc);
            acc = fmaf(v.z, fast_logf(fmaxf(v.z, 1e-8f)), acc);
            acc = fmaf(v.w, fast_logf(fmaxf(v.w, 1e-8f)), acc);
        }
        float s = block_reduce256(acc, s8);
        if (threadIdx.x == 0) atomicAdd(&g_acc[A_ENT_S], (double)(-s));
    } else {
        bid -= ENT_BLOCKS;
        for (int i = bid * 256 + threadIdx.x; i < N4; i += SQ_BLOCKS * 256) {
            float4 v = __ldg(&dt4[i]);
            acc = fmaf(v.x, v.x, acc);
            acc = fmaf(v.y, v.y, acc);
            acc = fmaf(v.z, v.z, acc);
            acc = fmaf(v.w, v.w, acc);
        }
        float s = block_reduce256(acc, s8);
        if (threadIdx.x == 0) atomicAdd(&g_acc[A_SQ], (double)s);
    }
}

// ---------------------------------------------------------------------------
// Consistency: one block per (b, pair(c<d)) = 240 blocks.
// Phase A: per-q match bitmask over the other camera's 256 slots (smem).
// Phase B: deterministic sweep over matched q's with full-block row math.
__global__ void consistency_kernel(const float* __restrict__ assoc) {
    __shared__ int qid_d[QQ];
    __shared__ unsigned mbits[QQ][8];   // 8 KB
    __shared__ int cntarr[QQ];
    __shared__ float s8[8];

    int blk = blockIdx.x;
    const int pr = blk % NPAIR;
    const int b  = blk / NPAIR;
    const int c = PAIR_C[pr];
    const int d = PAIR_D[pr];
    const int cbase = (b * CC + c) * QQ;
    const int dbase = (b * CC + d) * QQ;
    const int t = threadIdx.x;

    const int myqid = g_qids[cbase + t];   // -1 == invalid (this thread's q row)
    qid_d[t] = g_qids[dbase + t];
    __syncthreads();

    // Phase A: thread t builds match bitmask for q = t
    int cnt = 0;
    #pragma unroll
    for (int w = 0; w < 8; w++) {
        unsigned m = 0;
        if (myqid >= 0) {
            #pragma unroll 8
            for (int j = 0; j < 32; j++) {
                if (qid_d[w * 32 + j] == myqid) m |= (1u << j);
            }
        }
        mbits[t][w] = m;
        cnt += __popc(m);
    }
    cntarr[t] = cnt;
    __syncthreads();

    // Phase B: sweep matched q's (deterministic order)
    float con_local = 0.0f;   // meaningful in thread 0 only
    int   rows_local = 0;
    for (int q = 0; q < QQ; q++) {
        const int cq = cntarr[q];
        if (cq == 0) continue;
        float s = 0.0f;
        #pragma unroll
        for (int w = 0; w < 8; w++) {
            unsigned m = mbits[q][w];
            while (m) {
                int j = __ffs(m) - 1;
                m &= m - 1;
                s += __ldg(&assoc[(size_t)(dbase + w * 32 + j) * TT + t]);
            }
        }
        float peer = s / (float)cq;
        float diff = __ldg(&assoc[(size_t)(cbase + q) * TT + t]) - peer;
        float term = block_reduce256(diff * diff, s8);
        if (t == 0) { con_local += term * (1.0f / (float)TT); rows_local++; }
        __syncthreads();   // protect s8 reuse across iterations
    }
    if (t == 0 && rows_local > 0) {
        atomicAdd(&g_acc[A_CON_S], (double)con_local);
        atomicAdd(&g_acc[A_CON_C], (double)rows_local);
    }
}

// ---------------------------------------------------------------------------
// Finalize: combine all accumulators into the 6 output scalars.
__global__ void finalize_kernel(float* __restrict__ out, int out_size) {
    if (threadIdx.x != 0 || blockIdx.x != 0) return;
    double dn    = g_acc[A_SQ] / ((double)BB * CC * QQ * DD);
    double score = g_acc[A_BCE_S] / fmax(g_acc[A_BCE_C], 1.0);
    double boxl  = g_acc[A_BOX_S] / fmax(g_acc[A_BOX_C], 1.0);
    double sup   = score + boxl;
    double ent   = g_acc[A_ENT_S] / fmax(g_acc[A_ENT_C], 1.0);
    double pair  = g_acc[A_NLL_S] / fmax(g_acc[A_NLL_C], 1.0);
    double con   = g_acc[A_CON_S] / fmax(g_acc[A_CON_C], 1.0);
    double tot   = dn + sup + ent + pair + con;
    float vals[6] = {(float)tot, (float)dn, (float)sup, (float)ent, (float)pair, (float)con};
    int n = out_size < 6 ? out_size : 6;
    for (int i = 0; i < n; i++) out[i] = vals[i];
}

// ---------------------------------------------------------------------------
extern "C" void kernel_launch(void* const* d_in, const int* in_sizes, int n_in,
                              void* d_out, int out_size) {
    const float* det_tokens = (const float*)d_in[0];
    const float* det_scores = (const float*)d_in[1];
    const float* det_boxes  = (const float*)d_in[2];
    const float* assoc      = (const float*)d_in[3];
    const float* boxes      = (const float*)d_in[4];
    const unsigned char* cam_mask    = (const unsigned char*)d_in[5];
    const unsigned char* target_mask = (const unsigned char*)d_in[6];
    const int* ids = (const int*)d_in[7];
    const int* p_imgh = (n_in >= 10) ? (const int*)d_in[8] : nullptr;
    const int* p_imgw = (n_in >= 10) ? (const int*)d_in[9] : nullptr;
    float* out = (float*)d_out;

    init_kernel<<<1, 32>>>(cam_mask, target_mask);

    pack_kernel<<<BB * CC, QQ>>>(det_scores, det_boxes, assoc, boxes,
                                 cam_mask, target_mask, ids, p_imgh, p_imgw);

    stream_kernel<<<STREAM_BLOCKS, 256>>>((const float4*)assoc,
                                          (const float4*)det_tokens);

    consistency_kernel<<<BB * NPAIR, 256>>>(assoc);

    finalize_kernel<<<1, 32>>>(out, out_size);
}